// round 3
// baseline (speedup 1.0000x reference)
#include <cuda_runtime.h>

// Shapes (fixed by the problem)
#define BB 64
#define NN 21
#define HH 128
#define WW 128
// Total elements = 64*21*128*128 = 22,020,096 ; /4 = 5,505,024 float4

static constexpr int PART_BLOCKS = 1184;   // 148 SMs * 8
static constexpr int THREADS = 256;
static constexpr int NKP = BB * NN;        // 1344 keypoints

__device__ float g_mse_part[PART_BLOCKS];
__device__ float g_pck_part[PART_BLOCKS];
__device__ unsigned int g_done_ctr;        // zero-init at load; reset by last block

__device__ __forceinline__ float warp_sum(float v) {
    #pragma unroll
    for (int off = 16; off > 0; off >>= 1)
        v += __shfl_down_sync(0xFFFFFFFFu, v, off);
    return v;
}

__device__ __forceinline__ float sqdiff4(float4 a, float4 b, float acc) {
    float d;
    d = a.x - b.x; acc = fmaf(d, d, acc);
    d = a.y - b.y; acc = fmaf(d, d, acc);
    d = a.z - b.z; acc = fmaf(d, d, acc);
    d = a.w - b.w; acc = fmaf(d, d, acc);
    return acc;
}

__global__ void __launch_bounds__(THREADS) fused_loss_kernel(
    const float4* __restrict__ pred4,
    const float4* __restrict__ gt4,
    const float*  __restrict__ pred,   // scalar view for gathers
    const float*  __restrict__ kp,     // (B, N, 2) -> [x, y]
    float* __restrict__ out,
    int n4)
{
    const int tid_global = blockIdx.x * THREADS + threadIdx.x;
    const int stride = gridDim.x * THREADS;

    // ---- keypoint gather (overlapped with streaming; first NKP threads) ----
    float pck_acc = 0.0f;
    if (tid_global < NKP) {
        float xf = __ldg(&kp[2 * tid_global + 0]);
        float yf = __ldg(&kp[2 * tid_global + 1]);
        int x = (int)fminf(fmaxf(xf, 0.0f), (float)(WW - 1));
        int y = (int)fminf(fmaxf(yf, 0.0f), (float)(HH - 1));
        float v = __ldg(&pred[(tid_global * HH + y) * WW + x]);
        float e = 1.0f - v;
        pck_acc = e * e;
    }

    // ---- streaming MSE: 4-deep unroll, 4 independent accumulators ----
    float acc0 = 0.0f, acc1 = 0.0f, acc2 = 0.0f, acc3 = 0.0f;
    int i = tid_global;
    for (; i + 3 * stride < n4; i += 4 * stride) {
        // front-batch all 8 loads (evict-first: data is single-use)
        float4 a0 = __ldcs(&pred4[i]);
        float4 a1 = __ldcs(&pred4[i + stride]);
        float4 a2 = __ldcs(&pred4[i + 2 * stride]);
        float4 a3 = __ldcs(&pred4[i + 3 * stride]);
        float4 b0 = __ldcs(&gt4[i]);
        float4 b1 = __ldcs(&gt4[i + stride]);
        float4 b2 = __ldcs(&gt4[i + 2 * stride]);
        float4 b3 = __ldcs(&gt4[i + 3 * stride]);
        acc0 = sqdiff4(a0, b0, acc0);
        acc1 = sqdiff4(a1, b1, acc1);
        acc2 = sqdiff4(a2, b2, acc2);
        acc3 = sqdiff4(a3, b3, acc3);
    }
    for (; i < n4; i += stride) {
        float4 a = __ldcs(&pred4[i]);
        float4 b = __ldcs(&gt4[i]);
        acc0 = sqdiff4(a, b, acc0);
    }
    float mse_acc = (acc0 + acc1) + (acc2 + acc3);

    // ---- block reduction of both accumulators ----
    __shared__ float s1[THREADS / 32];
    __shared__ float s2[THREADS / 32];
    int lane = threadIdx.x & 31;
    int wid  = threadIdx.x >> 5;
    float m = warp_sum(mse_acc);
    float p = warp_sum(pck_acc);
    if (lane == 0) { s1[wid] = m; s2[wid] = p; }
    __syncthreads();

    __shared__ bool s_is_last;
    if (wid == 0) {
        float mm = (lane < THREADS / 32) ? s1[lane] : 0.0f;
        float pp = (lane < THREADS / 32) ? s2[lane] : 0.0f;
        mm = warp_sum(mm);
        pp = warp_sum(pp);
        if (lane == 0) {
            g_mse_part[blockIdx.x] = mm;
            g_pck_part[blockIdx.x] = pp;
            __threadfence();
            unsigned int prev = atomicAdd(&g_done_ctr, 1u);
            s_is_last = (prev == (unsigned int)(gridDim.x - 1));
        }
    }
    __syncthreads();

    // ---- last block finalizes ----
    if (s_is_last) {
        float ma = 0.0f, pa = 0.0f;
        for (int j = threadIdx.x; j < PART_BLOCKS; j += THREADS) {
            ma += g_mse_part[j];
            pa += g_pck_part[j];
        }
        float mw = warp_sum(ma);
        float pw = warp_sum(pa);
        if (lane == 0) { s1[wid] = mw; s2[wid] = pw; }
        __syncthreads();
        if (wid == 0) {
            float mm = (lane < THREADS / 32) ? s1[lane] : 0.0f;
            float pp = (lane < THREADS / 32) ? s2[lane] : 0.0f;
            mm = warp_sum(mm);
            pp = warp_sum(pp);
            if (lane == 0) {
                float mse = mm / (float)((long long)BB * NN * HH * WW);
                float pck = pp / (float)NKP;
                out[0] = mse + pck;   // total (weights are 1.0)
                out[1] = mse;
                out[2] = pck;
                g_done_ctr = 0;       // reset for next graph replay
            }
        }
    }
}

extern "C" void kernel_launch(void* const* d_in, const int* in_sizes, int n_in,
                              void* d_out, int out_size)
{
    const float* pred = (const float*)d_in[0];
    const float* gt   = (const float*)d_in[1];
    const float* kp   = (const float*)d_in[2];
    float* out = (float*)d_out;

    int n4 = (BB * NN * HH * WW) / 4;   // 5,505,024

    fused_loss_kernel<<<PART_BLOCKS, THREADS>>>(
        (const float4*)pred, (const float4*)gt, pred, kp, out, n4);
}